// round 15
// baseline (speedup 1.0000x reference)
#include <cuda_runtime.h>
#include <math.h>
#include <stdint.h>

#define B_    64
#define U_    512
#define CORE_ 512
#define UNIT_ 256
#define HID_  1024
#define ACT_  12
#define M_    (B_*U_)

// -------------------- scratch (device globals; no allocs) -------------------
__device__ float g_core_part[B_ * HID_];   // core@W1[256:768]+b1  [64,1024]
__device__ float g_W1t[HID_ * UNIT_];      // W1[0:256,:]^T, tf32-rounded [1024,256]

// -------------------- PTX helpers (plain-sm_103-safe) -----------------------
__device__ __forceinline__ uint32_t smem_u32(const void* p) {
    uint32_t a;
    asm("{ .reg .u64 t; cvta.to.shared.u64 t, %1; cvt.u32.u64 %0, t; }" : "=r"(a) : "l"(p));
    return a;
}
#define CP_ASYNC16(dst, src) \
    asm volatile("cp.async.ca.shared.global [%0], [%1], 16;" :: "r"(dst), "l"(src))
#define CP_COMMIT()  asm volatile("cp.async.commit_group;" ::: "memory")
#define CP_WAIT1()   asm volatile("cp.async.wait_group 1;" ::: "memory")
#define CP_WAIT0()   asm volatile("cp.async.wait_group 0;" ::: "memory")

__device__ __forceinline__ void ldsm_x4(uint32_t& r0, uint32_t& r1, uint32_t& r2,
                                        uint32_t& r3, uint32_t addr) {
    asm volatile("ldmatrix.sync.aligned.m8n8.x4.shared.b16 {%0,%1,%2,%3}, [%4];"
                 : "=r"(r0), "=r"(r1), "=r"(r2), "=r"(r3) : "r"(addr));
}
__device__ __forceinline__ void mma_tf32(float* c, const uint32_t* a,
                                         uint32_t b0, uint32_t b1) {
    asm volatile("mma.sync.aligned.m16n8k8.row.col.f32.tf32.tf32.f32 "
                 "{%0,%1,%2,%3},{%4,%5,%6,%7},{%8,%9},{%0,%1,%2,%3};"
                 : "+f"(c[0]), "+f"(c[1]), "+f"(c[2]), "+f"(c[3])
                 : "r"(a[0]), "r"(a[1]), "r"(a[2]), "r"(a[3]), "r"(b0), "r"(b1));
}
__device__ __forceinline__ uint32_t f2tf32(uint32_t x) {
    uint32_t r;
    asm("cvt.rna.tf32.f32 %0, %1;" : "=r"(r) : "f"(__uint_as_float(x)));
    return r;
}

// ---------------------------------------------------------------------------
// Kernel A: transpose W1[0:256,:] -> g_W1t[n][k], tf32-rounded.
// ---------------------------------------------------------------------------
__global__ __launch_bounds__(256) void transpose_kernel(const float* __restrict__ W1) {
    __shared__ float t[32][33];
    int k0 = blockIdx.x * 32, n0 = blockIdx.y * 32;
    int tx = threadIdx.x & 31, ty = threadIdx.x >> 5;
#pragma unroll
    for (int j = ty; j < 32; j += 8)
        t[j][tx] = W1[(size_t)(k0 + j) * HID_ + n0 + tx];
    __syncthreads();
#pragma unroll
    for (int j = ty; j < 32; j += 8) {
        uint32_t r = f2tf32(__float_as_uint(t[tx][j]));
        g_W1t[(size_t)(n0 + j) * UNIT_ + k0 + tx] = __uint_as_float(r);
    }
}

// ---------------------------------------------------------------------------
// Kernel B: core_part[b][h] = core[b] @ W1[256:768][h] + b1[h]   (fp32 exact)
// ---------------------------------------------------------------------------
__global__ __launch_bounds__(512) void core_part_kernel(
    const float* __restrict__ core, const float* __restrict__ W1,
    const float* __restrict__ b1) {
    __shared__ float red[512];
    int b  = blockIdx.y;
    int h  = blockIdx.x * 128 + (threadIdx.x & 127);
    int kg = threadIdx.x >> 7;
    const float* c = core + b * CORE_ + kg * 128;
    const float* w = W1 + (size_t)(UNIT_ + kg * 128) * HID_ + h;
    float acc = 0.f;
#pragma unroll 16
    for (int k = 0; k < 128; k++)
        acc = fmaf(__ldg(c + k), w[(size_t)k * HID_], acc);
    red[threadIdx.x] = acc;
    __syncthreads();
    if (threadIdx.x < 128) {
        g_core_part[b * HID_ + h] = red[threadIdx.x] + red[threadIdx.x + 128] +
                                    red[threadIdx.x + 256] + red[threadIdx.x + 384] + b1[h];
    }
}

// ---------------------------------------------------------------------------
// Kernel C: hidden = relu(emb @ W1t^T + core_part)  via mma.sync tf32
// Block 128x128, K-chunks of 32 (double-buffered cp.async), 8 warps (4M x 2N).
// (Exact R9 version — known 2 CTA/SM, no spills.)
// ---------------------------------------------------------------------------
#define STG_A   16384
#define STG_B   16384
#define SM_A0   0
#define SM_B0   32768
#define SM_CPS  65536
#define SM_TOT  (65536 + 512)

__global__ __launch_bounds__(256, 2) void gemm1_kernel(
    const float* __restrict__ emb, float* __restrict__ out_emb) {
    extern __shared__ char smem[];
    uint32_t sbase = smem_u32(smem);
    float* cps = (float*)(smem + SM_CPS);

    int tid  = threadIdx.x;
    int lane = tid & 31, wid = tid >> 5;
    int wm   = wid & 3;
    int wn   = wid >> 2;
    int m0   = blockIdx.x * 128;
    int n0   = blockIdx.y * 128;
    int b    = blockIdx.x >> 2;

    if (tid < 128) cps[tid] = g_core_part[b * HID_ + n0 + tid];

    const float* srcA = emb + (size_t)m0 * UNIT_;
    const float* srcB = g_W1t + (size_t)n0 * UNIT_;

    int rowA  = wm * 32 + (lane & 15);
    int chA   = lane >> 4;
    int rowB  = wn * 64 + ((lane >> 4) << 3) + (lane & 7);
    int chB   = (lane >> 3) & 1;

    float c[2][8][4];
#pragma unroll
    for (int mf = 0; mf < 2; mf++)
#pragma unroll
        for (int nf = 0; nf < 8; nf++)
#pragma unroll
            for (int j = 0; j < 4; j++) c[mf][nf][j] = 0.f;

    auto issue = [&](int kc, int s) {
#pragma unroll
        for (int i = 0; i < 4; i++) {
            int e = tid + i * 256;
            int r = e >> 3, ch = e & 7;
            uint32_t dst = sbase + SM_A0 + s * STG_A + r * 128 + (((uint32_t)(ch ^ (r & 7))) << 4);
            CP_ASYNC16(dst, srcA + (size_t)r * UNIT_ + kc * 32 + ch * 4);
        }
#pragma unroll
        for (int i = 0; i < 4; i++) {
            int e = tid + i * 256;
            int r = e >> 3, ch = e & 7;
            uint32_t dst = sbase + SM_B0 + s * STG_B + r * 128 + (((uint32_t)(ch ^ (r & 7))) << 4);
            CP_ASYNC16(dst, srcB + (size_t)r * UNIT_ + kc * 32 + ch * 4);
        }
        CP_COMMIT();
    };

    issue(0, 0);

#pragma unroll 1
    for (int kc = 0; kc < UNIT_ / 32; kc++) {
        int s = kc & 1;
        if (kc + 1 < UNIT_ / 32) { issue(kc + 1, s ^ 1); CP_WAIT1(); }
        else                     { CP_WAIT0(); }
        __syncthreads();

        uint32_t abase = sbase + SM_A0 + s * STG_A;
        uint32_t bbase = sbase + SM_B0 + s * STG_B;
#pragma unroll
        for (int ks = 0; ks < 4; ks++) {
            uint32_t a[2][4];
#pragma unroll
            for (int mf = 0; mf < 2; mf++) {
                int r = rowA + mf * 16;
                int ch = ks * 2 + chA;
                uint32_t addr = abase + r * 128 + (((uint32_t)(ch ^ (r & 7))) << 4);
                ldsm_x4(a[mf][0], a[mf][1], a[mf][2], a[mf][3], addr);
#pragma unroll
                for (int j = 0; j < 4; j++) a[mf][j] = f2tf32(a[mf][j]);
            }
#pragma unroll
            for (int nfp = 0; nfp < 4; nfp++) {
                int r = rowB + nfp * 16;
                int ch = ks * 2 + chB;
                uint32_t addr = bbase + r * 128 + (((uint32_t)(ch ^ (r & 7))) << 4);
                uint32_t b0, b1, b2, b3;
                ldsm_x4(b0, b1, b2, b3, addr);
#pragma unroll
                for (int mf = 0; mf < 2; mf++) {
                    mma_tf32(c[mf][nfp * 2 + 0], a[mf], b0, b1);
                    mma_tf32(c[mf][nfp * 2 + 1], a[mf], b2, b3);
                }
            }
        }
        __syncthreads();
    }

    int g   = lane >> 2;
    int tig = lane & 3;
#pragma unroll
    for (int mf = 0; mf < 2; mf++) {
        int r0g = m0 + wm * 32 + mf * 16 + g;
#pragma unroll
        for (int nf = 0; nf < 8; nf++) {
            int colL = wn * 64 + nf * 8 + tig * 2;
            float cp0 = cps[colL], cp1 = cps[colL + 1];
            float2 v0, v1;
            v0.x = fmaxf(c[mf][nf][0] + cp0, 0.f);
            v0.y = fmaxf(c[mf][nf][1] + cp1, 0.f);
            v1.x = fmaxf(c[mf][nf][2] + cp0, 0.f);
            v1.y = fmaxf(c[mf][nf][3] + cp1, 0.f);
            *(float2*)(out_emb + (size_t)r0g * HID_ + n0 + colL)       = v0;
            *(float2*)(out_emb + (size_t)(r0g + 8) * HID_ + n0 + colL) = v1;
        }
    }
}

// ---------------------------------------------------------------------------
// Kernel D: head — split-action scheme to cut register pressure.
// 8 warps/block, 16 rows/block. Warp pair (2g, 2g+1) covers rows rowb..rowb+3:
// warp handles 6 of the 12 actions -> acc[24] + wv[24] regs (vs 48+48 before).
// Softmax + range-mask finish per block from smem logits.
// ---------------------------------------------------------------------------
__global__ __launch_bounds__(256) void head_kernel(
    const float* __restrict__ hidden, const float* __restrict__ W2,
    const float* __restrict__ b2, const int* __restrict__ nr_units,
    const int* __restrict__ nr_own_flags, float* __restrict__ probs) {
    __shared__ float W2t[ACT_ * HID_];   // [a][k], 48KB
    __shared__ float lg[16][ACT_];

    for (int idx = threadIdx.x; idx < HID_ * ACT_; idx += 256) {
        int k = idx / ACT_, a = idx % ACT_;
        W2t[a * HID_ + k] = W2[idx];
    }
    __syncthreads();

    int lane = threadIdx.x & 31, warp = threadIdx.x >> 5;
    int rg   = warp >> 1;            // row group 0..3
    int ah   = (warp & 1) * 6;       // action half: 0 or 6
    int rowb = blockIdx.x * 16 + rg * 4;

    float acc[24];
#pragma unroll
    for (int i = 0; i < 24; i++) acc[i] = 0.f;

#pragma unroll
    for (int j = 0; j < 8; j++) {
        int k = j * 128 + lane * 4;
        float4 wv[6];
#pragma unroll
        for (int a = 0; a < 6; a++) wv[a] = *(const float4*)(&W2t[(ah + a) * HID_ + k]);
#pragma unroll
        for (int rr = 0; rr < 4; rr++) {
            float4 h = *(const float4*)(hidden + (size_t)(rowb + rr) * HID_ + k);
#pragma unroll
            for (int a = 0; a < 6; a++) {
                float s = acc[rr * 6 + a];
                s = fmaf(h.x, wv[a].x, s);
                s = fmaf(h.y, wv[a].y, s);
                s = fmaf(h.z, wv[a].z, s);
                s = fmaf(h.w, wv[a].w, s);
                acc[rr * 6 + a] = s;
            }
        }
    }
#pragma unroll
    for (int i = 0; i < 24; i++) {
#pragma unroll
        for (int off = 16; off; off >>= 1)
            acc[i] += __shfl_xor_sync(0xffffffffu, acc[i], off);
    }
    if (lane < 4) {   // lane rr writes its row's 6 actions
#pragma unroll
        for (int a = 0; a < 6; a++)
            lg[rg * 4 + lane][ah + a] = acc[lane * 6 + a];
    }
    __syncthreads();

    if (threadIdx.x < 16) {
        int row = blockIdx.x * 16 + threadIdx.x;
        int b = row >> 9, u = row & 511;
        float v[ACT_], m = -3.402823e38f;
#pragma unroll
        for (int a = 0; a < ACT_; a++) {
            v[a] = lg[threadIdx.x][a] + b2[a];
            m = fmaxf(m, v[a]);
        }
        float s = 0.f;
#pragma unroll
        for (int a = 0; a < ACT_; a++) { v[a] = expf(v[a] - m); s += v[a]; }
        bool valid = (u >= nr_own_flags[b]) && (u < nr_units[b]);
        float f = (valid ? 1.0f : 1e-9f) / s;
        float4* o = (float4*)(probs + (size_t)row * ACT_);
        o[0] = make_float4(v[0] * f, v[1] * f, v[2] * f, v[3] * f);
        o[1] = make_float4(v[4] * f, v[5] * f, v[6] * f, v[7] * f);
        o[2] = make_float4(v[8] * f, v[9] * f, v[10] * f, v[11] * f);
    }
}

// ---------------------------------------------------------------------------
extern "C" void kernel_launch(void* const* d_in, const int* in_sizes, int n_in,
                              void* d_out, int out_size) {
    const float* core = (const float*)d_in[0];
    const float* emb  = (const float*)d_in[1];
    const int*   nru  = (const int*)d_in[2];
    const int*   nrf  = (const int*)d_in[3];
    const float* W1   = (const float*)d_in[4];
    const float* b1   = (const float*)d_in[5];
    const float* W2   = (const float*)d_in[6];
    const float* b2   = (const float*)d_in[7];

    float* probs   = (float*)d_out;
    float* out_emb = (float*)d_out + (size_t)M_ * ACT_;

    cudaFuncSetAttribute(gemm1_kernel, cudaFuncAttributeMaxDynamicSharedMemorySize, SM_TOT);

    { dim3 g(UNIT_ / 32, HID_ / 32); transpose_kernel<<<g, 256>>>(W1); }
    { dim3 g(HID_ / 128, B_); core_part_kernel<<<g, 512>>>(core, W1, b1); }
    { dim3 g(M_ / 128, HID_ / 128); gemm1_kernel<<<g, 256, SM_TOT>>>(emb, out_emb); }
    head_kernel<<<M_ / 16, 256>>>(out_emb, W2, b2, nru, nrf, probs);
}

// round 16
// speedup vs baseline: 1.2561x; 1.2561x over previous
#include <cuda_runtime.h>
#include <math.h>
#include <stdint.h>

#define B_    64
#define U_    512
#define CORE_ 512
#define UNIT_ 256
#define HID_  1024
#define ACT_  12
#define M_    (B_*U_)

// -------------------- scratch (device globals; no allocs) -------------------
__device__ float g_core_part[B_ * HID_];   // core@W1[256:768]+b1  [64,1024]
__device__ float g_W1t[HID_ * UNIT_];      // W1[0:256,:]^T, tf32-rounded [1024,256]
__device__ float g_plog[8 * M_ * ACT_];    // partial logits per N-block [8][M][12]

// -------------------- PTX helpers (plain-sm_103-safe) -----------------------
__device__ __forceinline__ uint32_t smem_u32(const void* p) {
    uint32_t a;
    asm("{ .reg .u64 t; cvta.to.shared.u64 t, %1; cvt.u32.u64 %0, t; }" : "=r"(a) : "l"(p));
    return a;
}
#define CP_ASYNC16(dst, src) \
    asm volatile("cp.async.ca.shared.global [%0], [%1], 16;" :: "r"(dst), "l"(src))
#define CP_COMMIT()  asm volatile("cp.async.commit_group;" ::: "memory")
#define CP_WAIT1()   asm volatile("cp.async.wait_group 1;" ::: "memory")
#define CP_WAIT0()   asm volatile("cp.async.wait_group 0;" ::: "memory")

__device__ __forceinline__ void ldsm_x4(uint32_t& r0, uint32_t& r1, uint32_t& r2,
                                        uint32_t& r3, uint32_t addr) {
    asm volatile("ldmatrix.sync.aligned.m8n8.x4.shared.b16 {%0,%1,%2,%3}, [%4];"
                 : "=r"(r0), "=r"(r1), "=r"(r2), "=r"(r3) : "r"(addr));
}
__device__ __forceinline__ void mma_tf32(float* c, const uint32_t* a,
                                         uint32_t b0, uint32_t b1) {
    asm volatile("mma.sync.aligned.m16n8k8.row.col.f32.tf32.tf32.f32 "
                 "{%0,%1,%2,%3},{%4,%5,%6,%7},{%8,%9},{%0,%1,%2,%3};"
                 : "+f"(c[0]), "+f"(c[1]), "+f"(c[2]), "+f"(c[3])
                 : "r"(a[0]), "r"(a[1]), "r"(a[2]), "r"(a[3]), "r"(b0), "r"(b1));
}
__device__ __forceinline__ uint32_t f2tf32(uint32_t x) {
    uint32_t r;
    asm("cvt.rna.tf32.f32 %0, %1;" : "=r"(r) : "f"(__uint_as_float(x)));
    return r;
}

// ---------------------------------------------------------------------------
// Kernel A: transpose W1[0:256,:] -> g_W1t[n][k], tf32-rounded.
// ---------------------------------------------------------------------------
__global__ __launch_bounds__(256) void transpose_kernel(const float* __restrict__ W1) {
    __shared__ float t[32][33];
    int k0 = blockIdx.x * 32, n0 = blockIdx.y * 32;
    int tx = threadIdx.x & 31, ty = threadIdx.x >> 5;
#pragma unroll
    for (int j = ty; j < 32; j += 8)
        t[j][tx] = W1[(size_t)(k0 + j) * HID_ + n0 + tx];
    __syncthreads();
#pragma unroll
    for (int j = ty; j < 32; j += 8) {
        uint32_t r = f2tf32(__float_as_uint(t[tx][j]));
        g_W1t[(size_t)(n0 + j) * UNIT_ + k0 + tx] = __uint_as_float(r);
    }
}

// ---------------------------------------------------------------------------
// Kernel B: core_part[b][h] = core[b] @ W1[256:768][h] + b1[h]   (fp32 exact)
// ---------------------------------------------------------------------------
__global__ __launch_bounds__(512) void core_part_kernel(
    const float* __restrict__ core, const float* __restrict__ W1,
    const float* __restrict__ b1) {
    __shared__ float red[512];
    int b  = blockIdx.y;
    int h  = blockIdx.x * 128 + (threadIdx.x & 127);
    int kg = threadIdx.x >> 7;
    const float* c = core + b * CORE_ + kg * 128;
    const float* w = W1 + (size_t)(UNIT_ + kg * 128) * HID_ + h;
    float acc = 0.f;
#pragma unroll 16
    for (int k = 0; k < 128; k++)
        acc = fmaf(__ldg(c + k), w[(size_t)k * HID_], acc);
    red[threadIdx.x] = acc;
    __syncthreads();
    if (threadIdx.x < 128) {
        g_core_part[b * HID_ + h] = red[threadIdx.x] + red[threadIdx.x + 128] +
                                    red[threadIdx.x + 256] + red[threadIdx.x + 384] + b1[h];
    }
}

// ---------------------------------------------------------------------------
// Kernel C: hidden = relu(emb @ W1t^T + core_part) via mma.sync tf32,
// fused GEMM2 partials from a smem-staged hidden tile (fresh register scope).
// Block 128x128, K-chunks of 32 (double-buffered cp.async), 8 warps (4M x 2N).
// ---------------------------------------------------------------------------
#define STG_A   16384
#define STG_B   16384
#define SM_A0   0
#define SM_B0   32768
#define SM_HS   0                         // reuse A/B region: 128 x 132 floats
#define HS_STRIDE 132                     // 67584 B
#define SM_CPS  67584                     // 512 B
#define SM_W2S  68096                     // 128*12 floats = 6144 B
#define SM_TOT  74240

__global__ __launch_bounds__(256, 2) void gemm1_kernel(
    const float* __restrict__ emb, const float* __restrict__ W2,
    float* __restrict__ out_emb) {
    extern __shared__ char smem[];
    uint32_t sbase = smem_u32(smem);
    float* cps = (float*)(smem + SM_CPS);
    float* w2s = (float*)(smem + SM_W2S);
    float* hs  = (float*)(smem + SM_HS);

    int tid  = threadIdx.x;
    int lane = tid & 31, wid = tid >> 5;
    int wm   = wid & 3;
    int wn   = wid >> 2;
    int m0   = blockIdx.x * 128;
    int n0   = blockIdx.y * 128;
    int b    = blockIdx.x >> 2;

    if (tid < 128) cps[tid] = g_core_part[b * HID_ + n0 + tid];
#pragma unroll
    for (int i = tid; i < 128 * ACT_; i += 256) w2s[i] = W2[n0 * ACT_ + i];

    const float* srcA = emb + (size_t)m0 * UNIT_;
    const float* srcB = g_W1t + (size_t)n0 * UNIT_;

    int rowA  = wm * 32 + (lane & 15);
    int chA   = lane >> 4;
    int rowB  = wn * 64 + ((lane >> 4) << 3) + (lane & 7);
    int chB   = (lane >> 3) & 1;

    float c[2][8][4];
#pragma unroll
    for (int mf = 0; mf < 2; mf++)
#pragma unroll
        for (int nf = 0; nf < 8; nf++)
#pragma unroll
            for (int j = 0; j < 4; j++) c[mf][nf][j] = 0.f;

    auto issue = [&](int kc, int s) {
#pragma unroll
        for (int i = 0; i < 4; i++) {
            int e = tid + i * 256;
            int r = e >> 3, ch = e & 7;
            uint32_t dst = sbase + SM_A0 + s * STG_A + r * 128 + (((uint32_t)(ch ^ (r & 7))) << 4);
            CP_ASYNC16(dst, srcA + (size_t)r * UNIT_ + kc * 32 + ch * 4);
        }
#pragma unroll
        for (int i = 0; i < 4; i++) {
            int e = tid + i * 256;
            int r = e >> 3, ch = e & 7;
            uint32_t dst = sbase + SM_B0 + s * STG_B + r * 128 + (((uint32_t)(ch ^ (r & 7))) << 4);
            CP_ASYNC16(dst, srcB + (size_t)r * UNIT_ + kc * 32 + ch * 4);
        }
        CP_COMMIT();
    };

    issue(0, 0);

#pragma unroll 1
    for (int kc = 0; kc < UNIT_ / 32; kc++) {
        int s = kc & 1;
        if (kc + 1 < UNIT_ / 32) { issue(kc + 1, s ^ 1); CP_WAIT1(); }
        else                     { CP_WAIT0(); }
        __syncthreads();

        uint32_t abase = sbase + SM_A0 + s * STG_A;
        uint32_t bbase = sbase + SM_B0 + s * STG_B;
#pragma unroll
        for (int ks = 0; ks < 4; ks++) {
            uint32_t a[2][4];
#pragma unroll
            for (int mf = 0; mf < 2; mf++) {
                int r = rowA + mf * 16;
                int ch = ks * 2 + chA;
                uint32_t addr = abase + r * 128 + (((uint32_t)(ch ^ (r & 7))) << 4);
                ldsm_x4(a[mf][0], a[mf][1], a[mf][2], a[mf][3], addr);
#pragma unroll
                for (int j = 0; j < 4; j++) a[mf][j] = f2tf32(a[mf][j]);
            }
#pragma unroll
            for (int nfp = 0; nfp < 4; nfp++) {
                int r = rowB + nfp * 16;
                int ch = ks * 2 + chB;
                uint32_t addr = bbase + r * 128 + (((uint32_t)(ch ^ (r & 7))) << 4);
                uint32_t b0, b1, b2, b3;
                ldsm_x4(b0, b1, b2, b3, addr);
#pragma unroll
                for (int mf = 0; mf < 2; mf++) {
                    mma_tf32(c[mf][nfp * 2 + 0], a[mf], b0, b1);
                    mma_tf32(c[mf][nfp * 2 + 1], a[mf], b2, b3);
                }
            }
        }
        __syncthreads();
    }

    // ---- epilogue 1: + core_part, relu; store to gmem AND smem tile ----
    int g   = lane >> 2;
    int tig = lane & 3;
#pragma unroll
    for (int mf = 0; mf < 2; mf++) {
        int lr0 = wm * 32 + mf * 16 + g;          // local row
#pragma unroll
        for (int nf = 0; nf < 8; nf++) {
            int colL = wn * 64 + nf * 8 + tig * 2;
            float cp0 = cps[colL], cp1 = cps[colL + 1];
            float2 v0, v1;
            v0.x = fmaxf(c[mf][nf][0] + cp0, 0.f);
            v0.y = fmaxf(c[mf][nf][1] + cp1, 0.f);
            v1.x = fmaxf(c[mf][nf][2] + cp0, 0.f);
            v1.y = fmaxf(c[mf][nf][3] + cp1, 0.f);
            *(float2*)(out_emb + (size_t)(m0 + lr0) * HID_ + n0 + colL)     = v0;
            *(float2*)(out_emb + (size_t)(m0 + lr0 + 8) * HID_ + n0 + colL) = v1;
            *(float2*)(&hs[lr0 * HS_STRIDE + colL])       = v0;
            *(float2*)(&hs[(lr0 + 8) * HS_STRIDE + colL]) = v1;
        }
    }
    __syncthreads();

    // ---- epilogue 2 (fresh scope): partial logits from smem hidden tile ----
    {
        int lr    = wid * 16 + (lane & 15);       // local row 0..127
        int chalf = (lane >> 4) * 64;             // col half 0 / 64
        float p[ACT_];
#pragma unroll
        for (int a = 0; a < ACT_; a++) p[a] = 0.f;
        const float* hrow = &hs[lr * HS_STRIDE + chalf];
#pragma unroll 4
        for (int cc = 0; cc < 64; cc += 4) {
            float4 h = *(const float4*)(hrow + cc);
            const float4* w = (const float4*)(&w2s[(chalf + cc) * ACT_]);
            // w[0..2] = col cc actions 0..11; w[3..5] = col cc+1; etc.
            float4 w0a = w[0], w0b = w[1], w0c = w[2];
            float4 w1a = w[3], w1b = w[4], w1c = w[5];
            float4 w2a = w[6], w2b = w[7], w2c = w[8];
            float4 w3a = w[9], w3b = w[10], w3c = w[11];
            p[0]  = fmaf(h.x, w0a.x, fmaf(h.y, w1a.x, fmaf(h.z, w2a.x, fmaf(h.w, w3a.x, p[0]))));
            p[1]  = fmaf(h.x, w0a.y, fmaf(h.y, w1a.y, fmaf(h.z, w2a.y, fmaf(h.w, w3a.y, p[1]))));
            p[2]  = fmaf(h.x, w0a.z, fmaf(h.y, w1a.z, fmaf(h.z, w2a.z, fmaf(h.w, w3a.z, p[2]))));
            p[3]  = fmaf(h.x, w0a.w, fmaf(h.y, w1a.w, fmaf(h.z, w2a.w, fmaf(h.w, w3a.w, p[3]))));
            p[4]  = fmaf(h.x, w0b.x, fmaf(h.y, w1b.x, fmaf(h.z, w2b.x, fmaf(h.w, w3b.x, p[4]))));
            p[5]  = fmaf(h.x, w0b.y, fmaf(h.y, w1b.y, fmaf(h.z, w2b.y, fmaf(h.w, w3b.y, p[5]))));
            p[6]  = fmaf(h.x, w0b.z, fmaf(h.y, w1b.z, fmaf(h.z, w2b.z, fmaf(h.w, w3b.z, p[6]))));
            p[7]  = fmaf(h.x, w0b.w, fmaf(h.y, w1b.w, fmaf(h.z, w2b.w, fmaf(h.w, w3b.w, p[7]))));
            p[8]  = fmaf(h.x, w0c.x, fmaf(h.y, w1c.x, fmaf(h.z, w2c.x, fmaf(h.w, w3c.x, p[8]))));
            p[9]  = fmaf(h.x, w0c.y, fmaf(h.y, w1c.y, fmaf(h.z, w2c.y, fmaf(h.w, w3c.y, p[9]))));
            p[10] = fmaf(h.x, w0c.z, fmaf(h.y, w1c.z, fmaf(h.z, w2c.z, fmaf(h.w, w3c.z, p[10]))));
            p[11] = fmaf(h.x, w0c.w, fmaf(h.y, w1c.w, fmaf(h.z, w2c.w, fmaf(h.w, w3c.w, p[11]))));
        }
#pragma unroll
        for (int a = 0; a < ACT_; a++)
            p[a] += __shfl_xor_sync(0xffffffffu, p[a], 16);
        if (lane < 16) {
            float* dst = g_plog + ((size_t)blockIdx.y * M_ + m0 + lr) * ACT_;
#pragma unroll
            for (int a = 0; a < ACT_; a += 4)
                *(float4*)(dst + a) = make_float4(p[a], p[a + 1], p[a + 2], p[a + 3]);
        }
    }
}

// ---------------------------------------------------------------------------
// Kernel D: finisher — sum 8 partial logits, +b2, softmax, range mask.
// ---------------------------------------------------------------------------
__global__ __launch_bounds__(256) void softmax_kernel(
    const float* __restrict__ b2, const int* __restrict__ nr_units,
    const int* __restrict__ nr_own_flags, float* __restrict__ probs) {
    int r = blockIdx.x * 256 + threadIdx.x;
    float v[ACT_];
#pragma unroll
    for (int a = 0; a < ACT_; a++) v[a] = b2[a];
#pragma unroll
    for (int p = 0; p < 8; p++) {
        const float4* s = (const float4*)(g_plog + ((size_t)p * M_ + r) * ACT_);
        float4 a0 = s[0], a1 = s[1], a2 = s[2];
        v[0] += a0.x; v[1] += a0.y; v[2]  += a0.z; v[3]  += a0.w;
        v[4] += a1.x; v[5] += a1.y; v[6]  += a1.z; v[7]  += a1.w;
        v[8] += a2.x; v[9] += a2.y; v[10] += a2.z; v[11] += a2.w;
    }
    float m = -3.402823e38f;
#pragma unroll
    for (int a = 0; a < ACT_; a++) m = fmaxf(m, v[a]);
    float s = 0.f;
#pragma unroll
    for (int a = 0; a < ACT_; a++) { v[a] = expf(v[a] - m); s += v[a]; }
    int b = r >> 9, u = r & 511;
    bool valid = (u >= nr_own_flags[b]) && (u < nr_units[b]);
    float f = (valid ? 1.0f : 1e-9f) / s;
    float4* o = (float4*)(probs + (size_t)r * ACT_);
    o[0] = make_float4(v[0] * f, v[1] * f, v[2] * f, v[3] * f);
    o[1] = make_float4(v[4] * f, v[5] * f, v[6] * f, v[7] * f);
    o[2] = make_float4(v[8] * f, v[9] * f, v[10] * f, v[11] * f);
}

// ---------------------------------------------------------------------------
extern "C" void kernel_launch(void* const* d_in, const int* in_sizes, int n_in,
                              void* d_out, int out_size) {
    const float* core = (const float*)d_in[0];
    const float* emb  = (const float*)d_in[1];
    const int*   nru  = (const int*)d_in[2];
    const int*   nrf  = (const int*)d_in[3];
    const float* W1   = (const float*)d_in[4];
    const float* b1   = (const float*)d_in[5];
    const float* W2   = (const float*)d_in[6];
    const float* b2   = (const float*)d_in[7];

    float* probs   = (float*)d_out;
    float* out_emb = (float*)d_out + (size_t)M_ * ACT_;

    cudaFuncSetAttribute(gemm1_kernel, cudaFuncAttributeMaxDynamicSharedMemorySize, SM_TOT);

    { dim3 g(UNIT_ / 32, HID_ / 32); transpose_kernel<<<g, 256>>>(W1); }
    { dim3 g(HID_ / 128, B_); core_part_kernel<<<g, 512>>>(core, W1, b1); }
    { dim3 g(M_ / 128, HID_ / 128); gemm1_kernel<<<g, 256, SM_TOT>>>(emb, W2, out_emb); }
    softmax_kernel<<<M_ / 256, 256>>>(b2, nru, nrf, probs);
}